// round 14
// baseline (speedup 1.0000x reference)
#include <cuda_runtime.h>
#include <cuda_fp16.h>
#include <math.h>
#include <stdint.h>

// Problem constants
#define B_    128
#define P_    2048      // CL*H*W
#define NP_   32
#define NC_   10
#define K_    160       // NC_*CLO_

// Route geometry: 16 blocks per batch, 128 p per block
#define RT_BLOCKS_PER_B 16
#define RT_THREADS 256

// Scratch (allocation-free device globals; zero-initialized)
__device__ __align__(32) __half g_u[(size_t)B_ * P_ * K_];  // 83.9 MB, lives in L2
__device__ float  g_s[B_ * K_];
__device__ float  g_v[B_ * K_];
__device__ int    g_cnt[B_];                    // self-resetting completion counters

// ---------------------------------------------------------------------------
// L2 eviction-priority helpers. sm_103 ptxas: evict_last requires 256-bit
// (v4.b64) for BOTH ld and st. Streaming inputs use __ldcs.
// ---------------------------------------------------------------------------
__device__ __forceinline__ void ldg_el_32B(const void* p, uint4& q0, uint4& q1) {
    unsigned long long a, b, c, d;
    asm volatile("ld.global.nc.L2::evict_last.v4.b64 {%0,%1,%2,%3}, [%4];"
                 : "=l"(a), "=l"(b), "=l"(c), "=l"(d) : "l"(p));
    q0.x = (uint32_t)a; q0.y = (uint32_t)(a >> 32);
    q0.z = (uint32_t)b; q0.w = (uint32_t)(b >> 32);
    q1.x = (uint32_t)c; q1.y = (uint32_t)(c >> 32);
    q1.z = (uint32_t)d; q1.w = (uint32_t)(d >> 32);
}
__device__ __forceinline__ void stg_el_32B(void* p, uint4 v0, uint4 v1) {
    unsigned long long a = (unsigned long long)v0.x | ((unsigned long long)v0.y << 32);
    unsigned long long b = (unsigned long long)v0.z | ((unsigned long long)v0.w << 32);
    unsigned long long c = (unsigned long long)v1.x | ((unsigned long long)v1.y << 32);
    unsigned long long d = (unsigned long long)v1.z | ((unsigned long long)v1.w << 32);
    asm volatile("st.global.L2::evict_last.v4.b64 [%0], {%1,%2,%3,%4};"
                 :: "l"(p), "l"(a), "l"(b), "l"(c), "l"(d) : "memory");
}

// ---------------------------------------------------------------------------
// Packed f32x2 helpers (route)
// ---------------------------------------------------------------------------
__device__ __forceinline__ unsigned long long pack2(float lo, float hi) {
    unsigned long long r;
    asm("mov.b64 %0, {%1, %2};" : "=l"(r) : "f"(lo), "f"(hi));
    return r;
}
__device__ __forceinline__ void unpack2(unsigned long long v, float& lo, float& hi) {
    asm("mov.b64 {%0, %1}, %2;" : "=f"(lo), "=f"(hi) : "l"(v));
}
__device__ __forceinline__ void fma2(unsigned long long& d,
                                     unsigned long long a,
                                     unsigned long long b) {
    asm("fma.rn.f32x2 %0, %1, %2, %0;" : "+l"(d) : "l"(a), "l"(b));
}

// ---------------------------------------------------------------------------
// K1 (HMMA): per p, D[128 b][160 t] = squash(x)[128 b][32 n] @ W[32 n][160 t]
// via mma.sync.m16n8k16 (fp16 in, fp32 acc). 256 threads = 8 warps.
// Inputs read with __ldcs (streaming); u flushed with 256-bit evict_last.
// ---------------------------------------------------------------------------
#define SA 80
#define A_OFF 0                       // 128*80 = 10240
#define BOFF  10240                   // 160*80 = 12800, ends 23040
#define SSTG  336
#define SB_BYTES (128 * SSTG)         // 43008 (union covers A+B = 23040)

__device__ __forceinline__ void mma16816(float* c, uint32_t a0, uint32_t a1,
                                         uint32_t a2, uint32_t a3,
                                         uint32_t b0, uint32_t b1) {
    asm volatile(
        "mma.sync.aligned.m16n8k16.row.col.f32.f16.f16.f32 "
        "{%0,%1,%2,%3}, {%4,%5,%6,%7}, {%8,%9}, {%0,%1,%2,%3};"
        : "+f"(c[0]), "+f"(c[1]), "+f"(c[2]), "+f"(c[3])
        : "r"(a0), "r"(a1), "r"(a2), "r"(a3), "r"(b0), "r"(b1));
}

__global__ __launch_bounds__(256) void k1_mma(
    const float* __restrict__ tensor, const float* __restrict__ weight) {
    const int p = blockIdx.x;
    const int tid = threadIdx.x;
    const int wid = tid >> 5;
    const int lane = tid & 31;
    const int gid = lane >> 2;    // 0..7
    const int tig = lane & 3;     // 0..3

    __shared__ __align__(16) unsigned char sb[SB_BYTES];

    if (p == 0) {
        for (int i = tid; i < B_ * K_; i += 256) g_s[i] = 0.f;
    }

    // --- A fill: warp w rows b = 16w+i; lane = n. squash inline. ---
    const float* xbase = tensor + (size_t)p * NP_;
#pragma unroll
    for (int i = 0; i < 16; i++) {
        const int b = wid * 16 + i;
        const float x = __ldcs(xbase + (size_t)b * P_ * NP_ + lane);
        float ss = x * x;
        ss += __shfl_xor_sync(0xffffffffu, ss, 1);
        ss += __shfl_xor_sync(0xffffffffu, ss, 2);
        ss += __shfl_xor_sync(0xffffffffu, ss, 4);
        ss += __shfl_xor_sync(0xffffffffu, ss, 8);
        ss += __shfl_xor_sync(0xffffffffu, ss, 16);
        const float scale = ss / ((1.f + ss) * sqrtf(ss));
        *reinterpret_cast<__half*>(sb + A_OFF + b * SA + lane * 2) =
            __float2half(x * scale);
    }

    // --- B fill: thread owns row t (t=tid<160): Bt[t][k] = W[k][t]. ---
    const float* wbase = weight + (size_t)p * NP_ * K_;
    if (tid < K_) {
        float wv[NP_];
#pragma unroll
        for (int n = 0; n < NP_; n++) wv[n] = __ldcs(wbase + (size_t)n * K_ + tid);
        const int rowbase = BOFF + tid * SA;
#pragma unroll
        for (int j = 0; j < 8; j++) {
            uint2 d;
            __half2 h0 = __floats2half2_rn(wv[4 * j], wv[4 * j + 1]);
            __half2 h1 = __floats2half2_rn(wv[4 * j + 2], wv[4 * j + 3]);
            d.x = *reinterpret_cast<uint32_t*>(&h0);
            d.y = *reinterpret_cast<uint32_t*>(&h1);
            *reinterpret_cast<uint2*>(sb + rowbase + j * 8) = d;
        }
    }
    __syncthreads();

    // --- MMA: warp w = m-tile w; 20 n-tiles; 2 k-chunks ---
    float c[20][4];
#pragma unroll
    for (int nt = 0; nt < 20; nt++)
#pragma unroll
        for (int q = 0; q < 4; q++) c[nt][q] = 0.f;

#pragma unroll
    for (int kc = 0; kc < 2; kc++) {
        const int abase = A_OFF + (wid * 16 + gid) * SA + tig * 4 + kc * 32;
        const uint32_t a0 = *reinterpret_cast<const uint32_t*>(sb + abase);
        const uint32_t a1 = *reinterpret_cast<const uint32_t*>(sb + abase + 8 * SA);
        const uint32_t a2 = *reinterpret_cast<const uint32_t*>(sb + abase + 16);
        const uint32_t a3 = *reinterpret_cast<const uint32_t*>(sb + abase + 8 * SA + 16);
#pragma unroll
        for (int nt = 0; nt < 20; nt++) {
            const int bbase = BOFF + (nt * 8 + gid) * SA + tig * 4 + kc * 32;
            const uint32_t b0 = *reinterpret_cast<const uint32_t*>(sb + bbase);
            const uint32_t b1 = *reinterpret_cast<const uint32_t*>(sb + bbase + 16);
            mma16816(c[nt], a0, a1, a2, a3, b0, b1);
        }
    }
    __syncthreads();   // A/B reads done; smem reused as staging

    // --- Stage D as fp16 ---
    const int r0 = wid * 16 + gid;
#pragma unroll
    for (int nt = 0; nt < 20; nt++) {
        const int cb = (nt * 8 + tig * 2) * 2;
        __half2 h0 = __floats2half2_rn(c[nt][0], c[nt][1]);
        __half2 h1 = __floats2half2_rn(c[nt][2], c[nt][3]);
        *reinterpret_cast<uint32_t*>(sb + r0 * SSTG + cb) =
            *reinterpret_cast<uint32_t*>(&h0);
        *reinterpret_cast<uint32_t*>(sb + (r0 + 8) * SSTG + cb) =
            *reinterpret_cast<uint32_t*>(&h1);
    }
    __syncthreads();

    // --- Coalesced flush with 256-bit evict_last: 1280 chunks of 32B ---
#pragma unroll
    for (int it = 0; it < 5; it++) {
        const int idx = it * 256 + tid;
        const int row = idx / 10, col = idx % 10;     // col = 32B chunk in row
        const uint4* s = reinterpret_cast<const uint4*>(sb + row * SSTG + col * 32);
        stg_el_32B(reinterpret_cast<char*>(g_u + ((size_t)row * P_ + p) * K_) + col * 32,
                   s[0], s[1]);
    }
}

// ---------------------------------------------------------------------------
// Shared epilogue: last block for a given b squashes g_s.
// MODE 0: g_v = squash(s), zero s. MODE 1: g_v += squash(s), zero s
// (g_v becomes v0+v1 -> bias-free iter-2 logit). MODE 2: out = squash(s).
// ---------------------------------------------------------------------------
template <int MODE>
__device__ __forceinline__ void epilogue(int b, int tid, float* __restrict__ out) {
    __shared__ int s_done;
    __threadfence();
    __syncthreads();
    if (tid == 0)
        s_done = (atomicAdd(&g_cnt[b], 1) == RT_BLOCKS_PER_B - 1) ? 1 : 0;
    __syncthreads();
    if (!s_done) return;
    __threadfence();
    if (tid < K_) {
        const float sv = __ldcg(&g_s[b * K_ + tid]);
        float ss = sv * sv;
        ss += __shfl_xor_sync(0xffffffffu, ss, 1);
        ss += __shfl_xor_sync(0xffffffffu, ss, 2);
        ss += __shfl_xor_sync(0xffffffffu, ss, 4);
        ss += __shfl_xor_sync(0xffffffffu, ss, 8);
        const float scale = ss / ((1.f + ss) * sqrtf(ss));
        const float vv = sv * scale;
        if (MODE == 0) {
            g_v[b * K_ + tid] = vv;
            g_s[b * K_ + tid] = 0.f;
        } else if (MODE == 1) {
            g_v[b * K_ + tid] += vv;
            g_s[b * K_ + tid] = 0.f;
        } else {
            out[b * K_ + tid] = vv;
        }
    }
    if (tid == 0) g_cnt[b] = 0;
}

// ---------------------------------------------------------------------------
// Iter 0: s0 = (1/NC) * sum_p u[b,p,:]. Fully coalesced uint4 reads
// (L2 hits — lines pinned by k1's evict_last stores).
// 160 threads: chunk=tid%20, sub=tid/20 -> 8 stripes of 16 p; 128 p/block.
// ---------------------------------------------------------------------------
__global__ __launch_bounds__(160) void k_sum0() {
    const int b = blockIdx.y;
    const int tid = threadIdx.x;
    const int chunk = tid % 20;
    const int sub = tid / 20;
    const int p0 = blockIdx.x * 128 + sub * 16;

    float acc[8];
#pragma unroll
    for (int j = 0; j < 8; j++) acc[j] = 0.f;

#pragma unroll
    for (int i = 0; i < 16; i++) {
        const uint4 q = reinterpret_cast<const uint4*>(
            g_u + ((size_t)b * P_ + p0 + i) * K_)[chunk];
        const __half2* h = reinterpret_cast<const __half2*>(&q);
#pragma unroll
        for (int j = 0; j < 4; j++) {
            float2 f = __half22float2(h[j]);
            acc[2 * j] += f.x;
            acc[2 * j + 1] += f.y;
        }
    }

    __shared__ float s_red[8][K_];
#pragma unroll
    for (int j = 0; j < 8; j++) s_red[sub][chunk * 8 + j] = acc[j];
    __syncthreads();
    if (tid < K_) {
        float s = 0.f;
#pragma unroll
        for (int w = 0; w < 8; w++) s += s_red[w][tid];
        atomicAdd(&g_s[b * K_ + tid], s * (1.0f / NC_));
    }
    epilogue<0>(b, tid, nullptr);
}

// ---------------------------------------------------------------------------
// Routing pass (iters 1 and 2). Thread = (p, n); each 16-lane group
// processes TWO p's per j-step with independent register chains.
// u row (32B, aligned) loaded as one 256-bit evict_last LDG.
// ---------------------------------------------------------------------------
template <bool LAST>
__global__ __launch_bounds__(RT_THREADS) void k_route(float* __restrict__ out) {
    const int b   = blockIdx.y;
    const int tid = threadIdx.x;
    const int grp = tid >> 4;
    const int gl  = tid & 15;
    const int nn  = (gl < NC_) ? gl : 0;
    const bool act = (gl < NC_);
    const int warp = tid >> 5, lane = tid & 31;

    // v (loop-invariant) packed as half2
    __half2 vh[8];
    {
        const float4* vp = reinterpret_cast<const float4*>(g_v + b * K_ + nn * 16);
#pragma unroll
        for (int q = 0; q < 4; q++) {
            float4 t = vp[q];
            vh[2 * q]     = __floats2half2_rn(t.x, t.y);
            vh[2 * q + 1] = __floats2half2_rn(t.z, t.w);
        }
    }

    unsigned long long acc2[8];
#pragma unroll
    for (int i = 0; i < 8; i++) acc2[i] = 0ull;

    const int p_base = blockIdx.x * 128;
#pragma unroll
    for (int j = 0; j < 4; j++) {
        const int p0 = p_base + (2 * j) * 16 + grp;
        const int p1 = p_base + (2 * j + 1) * 16 + grp;

        uint4 qa0 = make_uint4(0, 0, 0, 0), qa1 = qa0, qb0 = qa0, qb1 = qa0;
        if (act) {
            ldg_el_32B(g_u + ((size_t)b * P_ + p0) * K_ + nn * 16, qa0, qa1);
            ldg_el_32B(g_u + ((size_t)b * P_ + p1) * K_ + nn * 16, qb0, qb1);
        }
        __half2 uha[8], uhb[8];
        {
            const __half2* a0 = reinterpret_cast<const __half2*>(&qa0);
            const __half2* a1 = reinterpret_cast<const __half2*>(&qa1);
            const __half2* b0 = reinterpret_cast<const __half2*>(&qb0);
            const __half2* b1 = reinterpret_cast<const __half2*>(&qb1);
#pragma unroll
            for (int i = 0; i < 4; i++) {
                uha[i] = a0[i]; uha[4 + i] = a1[i];
                uhb[i] = b0[i]; uhb[4 + i] = b1[i];
            }
        }

        // two independent logit dots (HFMA2, fp32 finish)
        __half2 dha = __hmul2(uha[0], vh[0]);
        __half2 dhb = __hmul2(uhb[0], vh[0]);
#pragma unroll
        for (int i = 1; i < 8; i++) {
            dha = __hfma2(uha[i], vh[i], dha);
            dhb = __hfma2(uhb[i], vh[i], dhb);
        }
        float2 dfa = __half22float2(dha);
        float2 dfb = __half22float2(dhb);
        const float da = dfa.x + dfa.y;
        const float db = dfb.x + dfb.y;

        // two interleaved softmax reductions (no max: logits bounded)
        float ea = act ? __expf(da) : 0.f;
        float eb = act ? __expf(db) : 0.f;
        float dena = ea, denb = eb;
        dena += __shfl_xor_sync(0xffffffffu, dena, 1);
        denb += __shfl_xor_sync(0xffffffffu, denb, 1);
        dena += __shfl_xor_sync(0xffffffffu, dena, 2);
        denb += __shfl_xor_sync(0xffffffffu, denb, 2);
        dena += __shfl_xor_sync(0xffffffffu, dena, 4);
        denb += __shfl_xor_sync(0xffffffffu, denb, 4);
        dena += __shfl_xor_sync(0xffffffffu, dena, 8);
        denb += __shfl_xor_sync(0xffffffffu, denb, 8);
        const float ca = ea / dena;
        const float cb = eb / denb;

        const unsigned long long ca2 = pack2(ca, ca);
        const unsigned long long cb2 = pack2(cb, cb);
#pragma unroll
        for (int i = 0; i < 8; i++) {
            float2 ufa = __half22float2(uha[i]);
            float2 ufb = __half22float2(uhb[i]);
            fma2(acc2[i], ca2, pack2(ufa.x, ufa.y));
            fma2(acc2[i], cb2, pack2(ufb.x, ufb.y));
        }
    }

    float acc[16];
#pragma unroll
    for (int i = 0; i < 8; i++) unpack2(acc2[i], acc[2 * i], acc[2 * i + 1]);

    // combine the two 16-lane groups (same (n,k), different p)
#pragma unroll
    for (int k = 0; k < 16; k++)
        acc[k] += __shfl_xor_sync(0xffffffffu, acc[k], 16);

    __shared__ float s_red[RT_THREADS / 32][K_];
    if (lane < 16 && act) {
#pragma unroll
        for (int k = 0; k < 16; k++) s_red[warp][nn * 16 + k] = acc[k];
    }
    __syncthreads();
    if (tid < K_) {
        float s = 0.f;
#pragma unroll
        for (int w = 0; w < RT_THREADS / 32; w++) s += s_red[w][tid];
        atomicAdd(&g_s[b * K_ + tid], s);
    }
    epilogue<LAST ? 2 : 1>(b, tid, out);
}

// ---------------------------------------------------------------------------
extern "C" void kernel_launch(void* const* d_in, const int* in_sizes, int n_in,
                              void* d_out, int out_size) {
    const float* tensor = (const float*)d_in[0];
    const float* weight = (const float*)d_in[1];
    float* out = (float*)d_out;

    k1_mma<<<P_, 256>>>(tensor, weight);

    dim3 rg(RT_BLOCKS_PER_B, B_);
    k_sum0<<<rg, 160>>>();                       // iter 0 (uniform c) + squash
    k_route<false><<<rg, RT_THREADS>>>(nullptr); // iter 1; g_v <- v0+v1
    k_route<true ><<<rg, RT_THREADS>>>(out);     // iter 2; emit output
}

// round 15
// speedup vs baseline: 1.0038x; 1.0038x over previous
#include <cuda_runtime.h>
#include <cuda_fp16.h>
#include <math.h>
#include <stdint.h>

// Problem constants
#define B_    128
#define P_    2048      // CL*H*W
#define NP_   32
#define NC_   10
#define K_    160       // NC_*CLO_

// Route geometry: 16 blocks per batch, 128 p per block
#define RT_BLOCKS_PER_B 16
#define RT_THREADS 256

// Scratch (allocation-free device globals; zero-initialized)
__device__ __align__(32) __half g_u[(size_t)B_ * P_ * K_];  // 83.9 MB, lives in L2
__device__ float  g_s[B_ * K_];
__device__ float  g_v[B_ * K_];
__device__ int    g_cnt[B_];                    // self-resetting completion counters

// ---------------------------------------------------------------------------
// L2 eviction-priority helpers. sm_103 ptxas: evict_last requires 256-bit
// (v4.b64) for BOTH ld and st. Streaming inputs use __ldcs.
// ---------------------------------------------------------------------------
__device__ __forceinline__ void ldg_el_32B(const void* p, uint4& q0, uint4& q1) {
    unsigned long long a, b, c, d;
    asm volatile("ld.global.nc.L2::evict_last.v4.b64 {%0,%1,%2,%3}, [%4];"
                 : "=l"(a), "=l"(b), "=l"(c), "=l"(d) : "l"(p));
    q0.x = (uint32_t)a; q0.y = (uint32_t)(a >> 32);
    q0.z = (uint32_t)b; q0.w = (uint32_t)(b >> 32);
    q1.x = (uint32_t)c; q1.y = (uint32_t)(c >> 32);
    q1.z = (uint32_t)d; q1.w = (uint32_t)(d >> 32);
}
__device__ __forceinline__ void stg_el_32B(void* p, uint4 v0, uint4 v1) {
    unsigned long long a = (unsigned long long)v0.x | ((unsigned long long)v0.y << 32);
    unsigned long long b = (unsigned long long)v0.z | ((unsigned long long)v0.w << 32);
    unsigned long long c = (unsigned long long)v1.x | ((unsigned long long)v1.y << 32);
    unsigned long long d = (unsigned long long)v1.z | ((unsigned long long)v1.w << 32);
    asm volatile("st.global.L2::evict_last.v4.b64 [%0], {%1,%2,%3,%4};"
                 :: "l"(p), "l"(a), "l"(b), "l"(c), "l"(d) : "memory");
}

// ---------------------------------------------------------------------------
// Packed f32x2 helpers (route)
// ---------------------------------------------------------------------------
__device__ __forceinline__ unsigned long long pack2(float lo, float hi) {
    unsigned long long r;
    asm("mov.b64 %0, {%1, %2};" : "=l"(r) : "f"(lo), "f"(hi));
    return r;
}
__device__ __forceinline__ void unpack2(unsigned long long v, float& lo, float& hi) {
    asm("mov.b64 {%0, %1}, %2;" : "=f"(lo), "=f"(hi) : "l"(v));
}
__device__ __forceinline__ void fma2(unsigned long long& d,
                                     unsigned long long a,
                                     unsigned long long b) {
    asm("fma.rn.f32x2 %0, %1, %2, %0;" : "+l"(d) : "l"(a), "l"(b));
}

// ---------------------------------------------------------------------------
// K1 (HMMA): per p, D[128 b][160 t] = squash(x)[128 b][32 n] @ W[32 n][160 t]
// via mma.sync.m16n8k16 (fp16 in, fp32 acc). 256 threads = 8 warps.
// Inputs read with __ldcs (streaming); u flushed with 256-bit evict_last.
// ---------------------------------------------------------------------------
#define SA 80
#define A_OFF 0                       // 128*80 = 10240
#define BOFF  10240                   // 160*80 = 12800, ends 23040
#define SSTG  336
#define SB_BYTES (128 * SSTG)         // 43008 (union covers A+B = 23040)

__device__ __forceinline__ void mma16816(float* c, uint32_t a0, uint32_t a1,
                                         uint32_t a2, uint32_t a3,
                                         uint32_t b0, uint32_t b1) {
    asm volatile(
        "mma.sync.aligned.m16n8k16.row.col.f32.f16.f16.f32 "
        "{%0,%1,%2,%3}, {%4,%5,%6,%7}, {%8,%9}, {%0,%1,%2,%3};"
        : "+f"(c[0]), "+f"(c[1]), "+f"(c[2]), "+f"(c[3])
        : "r"(a0), "r"(a1), "r"(a2), "r"(a3), "r"(b0), "r"(b1));
}

__global__ __launch_bounds__(256) void k1_mma(
    const float* __restrict__ tensor, const float* __restrict__ weight) {
    const int p = blockIdx.x;
    const int tid = threadIdx.x;
    const int wid = tid >> 5;
    const int lane = tid & 31;
    const int gid = lane >> 2;    // 0..7
    const int tig = lane & 3;     // 0..3

    __shared__ __align__(16) unsigned char sb[SB_BYTES];

    if (p == 0) {
        for (int i = tid; i < B_ * K_; i += 256) g_s[i] = 0.f;
    }

    // --- A fill: warp w rows b = 16w+i; lane = n. squash inline. ---
    const float* xbase = tensor + (size_t)p * NP_;
#pragma unroll
    for (int i = 0; i < 16; i++) {
        const int b = wid * 16 + i;
        const float x = __ldcs(xbase + (size_t)b * P_ * NP_ + lane);
        float ss = x * x;
        ss += __shfl_xor_sync(0xffffffffu, ss, 1);
        ss += __shfl_xor_sync(0xffffffffu, ss, 2);
        ss += __shfl_xor_sync(0xffffffffu, ss, 4);
        ss += __shfl_xor_sync(0xffffffffu, ss, 8);
        ss += __shfl_xor_sync(0xffffffffu, ss, 16);
        const float scale = ss / ((1.f + ss) * sqrtf(ss));
        *reinterpret_cast<__half*>(sb + A_OFF + b * SA + lane * 2) =
            __float2half(x * scale);
    }

    // --- B fill: thread owns row t (t=tid<160): Bt[t][k] = W[k][t]. ---
    const float* wbase = weight + (size_t)p * NP_ * K_;
    if (tid < K_) {
        float wv[NP_];
#pragma unroll
        for (int n = 0; n < NP_; n++) wv[n] = __ldcs(wbase + (size_t)n * K_ + tid);
        const int rowbase = BOFF + tid * SA;
#pragma unroll
        for (int j = 0; j < 8; j++) {
            uint2 d;
            __half2 h0 = __floats2half2_rn(wv[4 * j], wv[4 * j + 1]);
            __half2 h1 = __floats2half2_rn(wv[4 * j + 2], wv[4 * j + 3]);
            d.x = *reinterpret_cast<uint32_t*>(&h0);
            d.y = *reinterpret_cast<uint32_t*>(&h1);
            *reinterpret_cast<uint2*>(sb + rowbase + j * 8) = d;
        }
    }
    __syncthreads();

    // --- MMA: warp w = m-tile w; 20 n-tiles; 2 k-chunks ---
    float c[20][4];
#pragma unroll
    for (int nt = 0; nt < 20; nt++)
#pragma unroll
        for (int q = 0; q < 4; q++) c[nt][q] = 0.f;

#pragma unroll
    for (int kc = 0; kc < 2; kc++) {
        const int abase = A_OFF + (wid * 16 + gid) * SA + tig * 4 + kc * 32;
        const uint32_t a0 = *reinterpret_cast<const uint32_t*>(sb + abase);
        const uint32_t a1 = *reinterpret_cast<const uint32_t*>(sb + abase + 8 * SA);
        const uint32_t a2 = *reinterpret_cast<const uint32_t*>(sb + abase + 16);
        const uint32_t a3 = *reinterpret_cast<const uint32_t*>(sb + abase + 8 * SA + 16);
#pragma unroll
        for (int nt = 0; nt < 20; nt++) {
            const int bbase = BOFF + (nt * 8 + gid) * SA + tig * 4 + kc * 32;
            const uint32_t b0 = *reinterpret_cast<const uint32_t*>(sb + bbase);
            const uint32_t b1 = *reinterpret_cast<const uint32_t*>(sb + bbase + 16);
            mma16816(c[nt], a0, a1, a2, a3, b0, b1);
        }
    }
    __syncthreads();   // A/B reads done; smem reused as staging

    // --- Stage D as fp16 ---
    const int r0 = wid * 16 + gid;
#pragma unroll
    for (int nt = 0; nt < 20; nt++) {
        const int cb = (nt * 8 + tig * 2) * 2;
        __half2 h0 = __floats2half2_rn(c[nt][0], c[nt][1]);
        __half2 h1 = __floats2half2_rn(c[nt][2], c[nt][3]);
        *reinterpret_cast<uint32_t*>(sb + r0 * SSTG + cb) =
            *reinterpret_cast<uint32_t*>(&h0);
        *reinterpret_cast<uint32_t*>(sb + (r0 + 8) * SSTG + cb) =
            *reinterpret_cast<uint32_t*>(&h1);
    }
    __syncthreads();

    // --- Coalesced flush with 256-bit evict_last: 1280 chunks of 32B ---
#pragma unroll
    for (int it = 0; it < 5; it++) {
        const int idx = it * 256 + tid;
        const int row = idx / 10, col = idx % 10;     // col = 32B chunk in row
        const uint4* s = reinterpret_cast<const uint4*>(sb + row * SSTG + col * 32);
        stg_el_32B(reinterpret_cast<char*>(g_u + ((size_t)row * P_ + p) * K_) + col * 32,
                   s[0], s[1]);
    }
}

// ---------------------------------------------------------------------------
// Shared epilogue: last block for a given b squashes g_s.
// MODE 0: g_v = squash(s), zero s. MODE 1: g_v += squash(s), zero s
// (g_v becomes v0+v1 -> bias-free iter-2 logit). MODE 2: out = squash(s).
// ---------------------------------------------------------------------------
template <int MODE>
__device__ __forceinline__ void epilogue(int b, int tid, float* __restrict__ out) {
    __shared__ int s_done;
    __threadfence();
    __syncthreads();
    if (tid == 0)
        s_done = (atomicAdd(&g_cnt[b], 1) == RT_BLOCKS_PER_B - 1) ? 1 : 0;
    __syncthreads();
    if (!s_done) return;
    __threadfence();
    if (tid < K_) {
        const float sv = __ldcg(&g_s[b * K_ + tid]);
        float ss = sv * sv;
        ss += __shfl_xor_sync(0xffffffffu, ss, 1);
        ss += __shfl_xor_sync(0xffffffffu, ss, 2);
        ss += __shfl_xor_sync(0xffffffffu, ss, 4);
        ss += __shfl_xor_sync(0xffffffffu, ss, 8);
        const float scale = ss / ((1.f + ss) * sqrtf(ss));
        const float vv = sv * scale;
        if (MODE == 0) {
            g_v[b * K_ + tid] = vv;
            g_s[b * K_ + tid] = 0.f;
        } else if (MODE == 1) {
            g_v[b * K_ + tid] += vv;
            g_s[b * K_ + tid] = 0.f;
        } else {
            out[b * K_ + tid] = vv;
        }
    }
    if (tid == 0) g_cnt[b] = 0;
}

// ---------------------------------------------------------------------------
// Iter 0: s0 = (1/NC) * sum_p u[b,p,:]. Fully coalesced uint4 reads
// (L2 hits — lines pinned by k1's evict_last stores).
// 160 threads: chunk=tid%20, sub=tid/20 -> 8 stripes of 16 p; 128 p/block.
// ---------------------------------------------------------------------------
__global__ __launch_bounds__(160) void k_sum0() {
    const int b = blockIdx.y;
    const int tid = threadIdx.x;
    const int chunk = tid % 20;
    const int sub = tid / 20;
    const int p0 = blockIdx.x * 128 + sub * 16;

    float acc[8];
#pragma unroll
    for (int j = 0; j < 8; j++) acc[j] = 0.f;

#pragma unroll
    for (int i = 0; i < 16; i++) {
        const uint4 q = reinterpret_cast<const uint4*>(
            g_u + ((size_t)b * P_ + p0 + i) * K_)[chunk];
        const __half2* h = reinterpret_cast<const __half2*>(&q);
#pragma unroll
        for (int j = 0; j < 4; j++) {
            float2 f = __half22float2(h[j]);
            acc[2 * j] += f.x;
            acc[2 * j + 1] += f.y;
        }
    }

    __shared__ float s_red[8][K_];
#pragma unroll
    for (int j = 0; j < 8; j++) s_red[sub][chunk * 8 + j] = acc[j];
    __syncthreads();
    if (tid < K_) {
        float s = 0.f;
#pragma unroll
        for (int w = 0; w < 8; w++) s += s_red[w][tid];
        atomicAdd(&g_s[b * K_ + tid], s * (1.0f / NC_));
    }
    epilogue<0>(b, tid, nullptr);
}

// ---------------------------------------------------------------------------
// Routing pass (iters 1 and 2). Thread = (p, n); each 16-lane group
// processes TWO p's per j-step with independent register chains.
// u row (32B, aligned) loaded as one 256-bit evict_last LDG.
// ---------------------------------------------------------------------------
template <bool LAST>
__global__ __launch_bounds__(RT_THREADS) void k_route(float* __restrict__ out) {
    const int b   = blockIdx.y;
    const int tid = threadIdx.x;
    const int grp = tid >> 4;
    const int gl  = tid & 15;
    const int nn  = (gl < NC_) ? gl : 0;
    const bool act = (gl < NC_);
    const int warp = tid >> 5, lane = tid & 31;

    // v (loop-invariant) packed as half2
    __half2 vh[8];
    {
        const float4* vp = reinterpret_cast<const float4*>(g_v + b * K_ + nn * 16);
#pragma unroll
        for (int q = 0; q < 4; q++) {
            float4 t = vp[q];
            vh[2 * q]     = __floats2half2_rn(t.x, t.y);
            vh[2 * q + 1] = __floats2half2_rn(t.z, t.w);
        }
    }

    unsigned long long acc2[8];
#pragma unroll
    for (int i = 0; i < 8; i++) acc2[i] = 0ull;

    const int p_base = blockIdx.x * 128;
#pragma unroll
    for (int j = 0; j < 4; j++) {
        const int p0 = p_base + (2 * j) * 16 + grp;
        const int p1 = p_base + (2 * j + 1) * 16 + grp;

        uint4 qa0 = make_uint4(0, 0, 0, 0), qa1 = qa0, qb0 = qa0, qb1 = qa0;
        if (act) {
            ldg_el_32B(g_u + ((size_t)b * P_ + p0) * K_ + nn * 16, qa0, qa1);
            ldg_el_32B(g_u + ((size_t)b * P_ + p1) * K_ + nn * 16, qb0, qb1);
        }
        __half2 uha[8], uhb[8];
        {
            const __half2* a0 = reinterpret_cast<const __half2*>(&qa0);
            const __half2* a1 = reinterpret_cast<const __half2*>(&qa1);
            const __half2* b0 = reinterpret_cast<const __half2*>(&qb0);
            const __half2* b1 = reinterpret_cast<const __half2*>(&qb1);
#pragma unroll
            for (int i = 0; i < 4; i++) {
                uha[i] = a0[i]; uha[4 + i] = a1[i];
                uhb[i] = b0[i]; uhb[4 + i] = b1[i];
            }
        }

        // two independent logit dots (HFMA2, fp32 finish)
        __half2 dha = __hmul2(uha[0], vh[0]);
        __half2 dhb = __hmul2(uhb[0], vh[0]);
#pragma unroll
        for (int i = 1; i < 8; i++) {
            dha = __hfma2(uha[i], vh[i], dha);
            dhb = __hfma2(uhb[i], vh[i], dhb);
        }
        float2 dfa = __half22float2(dha);
        float2 dfb = __half22float2(dhb);
        const float da = dfa.x + dfa.y;
        const float db = dfb.x + dfb.y;

        // two interleaved softmax reductions (no max: logits bounded)
        float ea = act ? __expf(da) : 0.f;
        float eb = act ? __expf(db) : 0.f;
        float dena = ea, denb = eb;
        dena += __shfl_xor_sync(0xffffffffu, dena, 1);
        denb += __shfl_xor_sync(0xffffffffu, denb, 1);
        dena += __shfl_xor_sync(0xffffffffu, dena, 2);
        denb += __shfl_xor_sync(0xffffffffu, denb, 2);
        dena += __shfl_xor_sync(0xffffffffu, dena, 4);
        denb += __shfl_xor_sync(0xffffffffu, denb, 4);
        dena += __shfl_xor_sync(0xffffffffu, dena, 8);
        denb += __shfl_xor_sync(0xffffffffu, denb, 8);
        const float ca = ea / dena;
        const float cb = eb / denb;

        const unsigned long long ca2 = pack2(ca, ca);
        const unsigned long long cb2 = pack2(cb, cb);
#pragma unroll
        for (int i = 0; i < 8; i++) {
            float2 ufa = __half22float2(uha[i]);
            float2 ufb = __half22float2(uhb[i]);
            fma2(acc2[i], ca2, pack2(ufa.x, ufa.y));
            fma2(acc2[i], cb2, pack2(ufb.x, ufb.y));
        }
    }

    float acc[16];
#pragma unroll
    for (int i = 0; i < 8; i++) unpack2(acc2[i], acc[2 * i], acc[2 * i + 1]);

    // combine the two 16-lane groups (same (n,k), different p)
#pragma unroll
    for (int k = 0; k < 16; k++)
        acc[k] += __shfl_xor_sync(0xffffffffu, acc[k], 16);

    __shared__ float s_red[RT_THREADS / 32][K_];
    if (lane < 16 && act) {
#pragma unroll
        for (int k = 0; k < 16; k++) s_red[warp][nn * 16 + k] = acc[k];
    }
    __syncthreads();
    if (tid < K_) {
        float s = 0.f;
#pragma unroll
        for (int w = 0; w < RT_THREADS / 32; w++) s += s_red[w][tid];
        atomicAdd(&g_s[b * K_ + tid], s);
    }
    epilogue<LAST ? 2 : 1>(b, tid, out);
}

// ---------------------------------------------------------------------------
extern "C" void kernel_launch(void* const* d_in, const int* in_sizes, int n_in,
                              void* d_out, int out_size) {
    const float* tensor = (const float*)d_in[0];
    const float* weight = (const float*)d_in[1];
    float* out = (float*)d_out;

    k1_mma<<<P_, 256>>>(tensor, weight);

    dim3 rg(RT_BLOCKS_PER_B, B_);
    k_sum0<<<rg, 160>>>();                       // iter 0 (uniform c) + squash
    k_route<false><<<rg, RT_THREADS>>>(nullptr); // iter 1; g_v <- v0+v1
    k_route<true ><<<rg, RT_THREADS>>>(out);     // iter 2; emit output
}